// round 6
// baseline (speedup 1.0000x reference)
#include <cuda_runtime.h>
#include <math.h>
#include <stdint.h>

#define BB 8
#define CC 96
#define NN 3136
#define KK 9
#define KI 12     // per-thread candidate list length (pass 1)
#define NCAND 96  // 8 lists * KI per row

// ---------------- scratch (device globals: no allocations allowed) ----------
__device__ float g_y1[BB*CC*NN];
__device__ float g_y1t[BB*NN*CC];
__device__ float g_xnt[BB*NN*CC];
__device__ int   g_cand[BB*NN*NCAND];
__device__ int   g_idx[BB*NN*KK];
__device__ float g_cat[BB*2*CC*NN];
__device__ float g_y2[BB*2*CC*NN];
__device__ float g_t [BB*4*CC*NN];
__device__ float g_s1[BB*CC*NN];
__device__ float g_s2[BB*CC*NN];

// ---------------- generic 1x1-conv GEMM: out[b,o,n] = sum_c W[o,c] in[b,c,n] + bias[o]
#define TN 128
#define TO 32
#define TKC 32
__global__ void gemm_bias_kernel(const float* __restrict__ in, const float* __restrict__ W,
                                 const float* __restrict__ bias, float* __restrict__ out,
                                 int Cin, int Cout)
{
    int b  = blockIdx.z;
    int o0 = blockIdx.y * TO;
    int n0 = blockIdx.x * TN;
    const float* inb = in + (size_t)b * Cin * NN;
    float* outb      = out + (size_t)b * Cout * NN;

    __shared__ float Ws[TKC][TO + 1];
    __shared__ float Is[TKC][TN];

    int tid = threadIdx.x;
    int tx = tid & 31;
    int ty = tid >> 5;

    float acc[4][4];
    #pragma unroll
    for (int i = 0; i < 4; i++)
        #pragma unroll
        for (int j = 0; j < 4; j++) acc[i][j] = 0.f;

    for (int k0 = 0; k0 < Cin; k0 += TKC) {
        for (int i = tid; i < TO * TKC; i += 256) {
            int o = i >> 5, k = i & 31;
            Ws[k][o] = W[(size_t)(o0 + o) * Cin + k0 + k];
        }
        for (int i = tid; i < TKC * TN; i += 256) {
            int k = i >> 7, n = i & 127;
            int gn = n0 + n;
            Is[k][n] = (gn < NN) ? inb[(size_t)(k0 + k) * NN + gn] : 0.f;
        }
        __syncthreads();
        #pragma unroll 8
        for (int k = 0; k < TKC; k++) {
            float a0 = Ws[k][ty*4+0], a1 = Ws[k][ty*4+1];
            float a2 = Ws[k][ty*4+2], a3 = Ws[k][ty*4+3];
            float4 bv = *(const float4*)&Is[k][tx*4];
            acc[0][0] += a0*bv.x; acc[0][1] += a0*bv.y; acc[0][2] += a0*bv.z; acc[0][3] += a0*bv.w;
            acc[1][0] += a1*bv.x; acc[1][1] += a1*bv.y; acc[1][2] += a1*bv.z; acc[1][3] += a1*bv.w;
            acc[2][0] += a2*bv.x; acc[2][1] += a2*bv.y; acc[2][2] += a2*bv.z; acc[2][3] += a2*bv.w;
            acc[3][0] += a3*bv.x; acc[3][1] += a3*bv.y; acc[3][2] += a3*bv.z; acc[3][3] += a3*bv.w;
        }
        __syncthreads();
    }
    #pragma unroll
    for (int i = 0; i < 4; i++) {
        int o = o0 + ty*4 + i;
        float bb = bias[o];
        #pragma unroll
        for (int j = 0; j < 4; j++) {
            int n = n0 + tx*4 + j;
            if (n < NN) outb[(size_t)o * NN + n] = acc[i][j] + bb;
        }
    }
}

// ---------------- instance norm over N per (b,c) row, with fused epilogues
// EPI: 0=none, 1=gelu(exact), 2=relu, 3=add residual
#define NN4 (NN/4)
template<int EPI>
__global__ void inorm_kernel(const float* __restrict__ in, float* __restrict__ out,
                             const float* __restrict__ res)
{
    int row = blockIdx.x;
    const float4* x4 = (const float4*)(in + (size_t)row * NN);
    float4* y4       = (float4*)(out + (size_t)row * NN);
    const float4* r4 = res ? (const float4*)(res + (size_t)row * NN) : nullptr;

    float s = 0.f, ss = 0.f;
    for (int i = threadIdx.x; i < NN4; i += blockDim.x) {
        float4 v = x4[i];
        s  += v.x + v.y + v.z + v.w;
        ss += v.x*v.x + v.y*v.y + v.z*v.z + v.w*v.w;
    }
    __shared__ float red[2][32];
    #pragma unroll
    for (int o = 16; o; o >>= 1) {
        s  += __shfl_down_sync(0xffffffffu, s,  o);
        ss += __shfl_down_sync(0xffffffffu, ss, o);
    }
    int wid = threadIdx.x >> 5, lid = threadIdx.x & 31;
    if (!lid) { red[0][wid] = s; red[1][wid] = ss; }
    __syncthreads();
    if (wid == 0) {
        s  = (lid < (int)(blockDim.x >> 5)) ? red[0][lid] : 0.f;
        ss = (lid < (int)(blockDim.x >> 5)) ? red[1][lid] : 0.f;
        #pragma unroll
        for (int o = 16; o; o >>= 1) {
            s  += __shfl_down_sync(0xffffffffu, s,  o);
            ss += __shfl_down_sync(0xffffffffu, ss, o);
        }
        if (!lid) { red[0][0] = s; red[1][0] = ss; }
    }
    __syncthreads();
    float mean = red[0][0] * (1.f / NN);
    float var  = red[1][0] * (1.f / NN) - mean * mean;
    float rstd = rsqrtf(var + 1e-5f);
    for (int i = threadIdx.x; i < NN4; i += blockDim.x) {
        float4 v = x4[i];
        float o0 = (v.x - mean) * rstd, o1 = (v.y - mean) * rstd;
        float o2 = (v.z - mean) * rstd, o3 = (v.w - mean) * rstd;
        if (EPI == 1) {
            o0 = 0.5f*o0*(1.f + erff(o0*0.70710678118654752f));
            o1 = 0.5f*o1*(1.f + erff(o1*0.70710678118654752f));
            o2 = 0.5f*o2*(1.f + erff(o2*0.70710678118654752f));
            o3 = 0.5f*o3*(1.f + erff(o3*0.70710678118654752f));
        } else if (EPI == 2) {
            o0 = fmaxf(o0, 0.f); o1 = fmaxf(o1, 0.f);
            o2 = fmaxf(o2, 0.f); o3 = fmaxf(o3, 0.f);
        } else if (EPI == 3) {
            float4 r = r4[i];
            o0 += r.x; o1 += r.y; o2 += r.z; o3 += r.w;
        }
        y4[i] = make_float4(o0, o1, o2, o3);
    }
}

// ---------------- per-pixel L2 normalization -> TRANSPOSED output [b][n][c]
__global__ void colnorm_t_kernel(const float* __restrict__ y1, float* __restrict__ xnt)
{
    int b = blockIdx.y;
    int n = blockIdx.x * blockDim.x + threadIdx.x;
    if (n >= NN) return;
    const float* p = y1 + (size_t)b * CC * NN + n;
    float v[CC];
    float s = 0.f;
    #pragma unroll
    for (int c = 0; c < CC; c++) { v[c] = p[(size_t)c * NN]; s += v[c] * v[c]; }
    float rn = 1.f / fmaxf(sqrtf(s), 1e-12f);
    float4* q = (float4*)(xnt + ((size_t)b * NN + n) * CC);
    #pragma unroll
    for (int cq = 0; cq < CC/4; cq++)
        q[cq] = make_float4(v[4*cq]*rn, v[4*cq+1]*rn, v[4*cq+2]*rn, v[4*cq+3]*rn);
}

// ---------------- tiled transpose: [b][C][N] -> [b][N][C]
__global__ void transpose_kernel(const float* __restrict__ in, float* __restrict__ out)
{
    __shared__ float tile[32][33];
    int b  = blockIdx.z;
    int n0 = blockIdx.x * 32;
    int c0 = blockIdx.y * 32;
    int x = threadIdx.x, y = threadIdx.y;   // 32 x 8
    #pragma unroll
    for (int i = 0; i < 32; i += 8) {
        int c = c0 + y + i, n = n0 + x;
        tile[y + i][x] = (c < CC && n < NN) ? in[(size_t)b*CC*NN + (size_t)c*NN + n] : 0.f;
    }
    __syncthreads();
    #pragma unroll
    for (int i = 0; i < 32; i += 8) {
        int n = n0 + y + i, c = c0 + x;
        if (n < NN && c < CC)
            out[(size_t)b*NN*CC + (size_t)n*CC + c] = tile[x][y + i];
    }
}

// ---------------- PASS 1: tf32 MMA distance GEMM + per-thread top-12 candidates
// score(n,m) = rp[n,m] - 2*dot(xn_n, xn_m)  (sq terms == 1; ordering identical)
#define KTR 128
#define KTC 128
#define AST 104                               // smem row stride (floats), conflict-free LDS.64
#define PL  (KTR*AST)
#define SMEM_KNN (2 * PL * 4)                 // A + B planes (tf32 bits)

__device__ __forceinline__ unsigned f2tf(float v) {
    unsigned r;
    asm("cvt.rna.tf32.f32 %0, %1;" : "=r"(r) : "f"(v));
    return r;
}

__device__ __forceinline__ void mma_tf32(float c[4],
    unsigned a0, unsigned a1, unsigned a2, unsigned a3, unsigned b0, unsigned b1)
{
    asm volatile(
        "mma.sync.aligned.m16n8k8.row.col.f32.tf32.tf32.f32 "
        "{%0,%1,%2,%3},{%4,%5,%6,%7},{%8,%9},{%0,%1,%2,%3};"
        : "+f"(c[0]), "+f"(c[1]), "+f"(c[2]), "+f"(c[3])
        : "r"(a0), "r"(a1), "r"(a2), "r"(a3), "r"(b0), "r"(b1));
}

__device__ __forceinline__ void ins12(float (&bv)[KI], int (&bi)[KI], float s, int c)
{
    if (s < bv[KI-1]) {
        bv[KI-1] = s; bi[KI-1] = c;
        #pragma unroll
        for (int k = KI-1; k > 0; k--) {
            if (bv[k] < bv[k-1]) {
                float tv = bv[k]; bv[k] = bv[k-1]; bv[k-1] = tv;
                int   ti = bi[k]; bi[k] = bi[k-1]; bi[k-1] = ti;
            }
        }
    }
}

// k-pair permutation within 8-group: element k -> pos 2*(k&3) + ((k>>2)&1)
__global__ void __launch_bounds__(512, 1)
knn_mma_kernel(const float* __restrict__ xnt, const float* __restrict__ rp,
               int* __restrict__ cand)
{
    extern __shared__ unsigned smu[];
    unsigned* As = smu;
    unsigned* Bs = smu + PL;

    int b  = blockIdx.y;
    int r0 = blockIdx.x * KTR;
    const float* xb = xnt + (size_t)b * NN * CC;
    int tid  = threadIdx.x;
    int warp = tid >> 5, lane = tid & 31;
    int g = lane >> 2, th = lane & 3;
    int wrow = (warp >> 1) * 16;
    int cw   = warp & 1;

    // ---- stage A tile (rows r0..r0+127), tf32, k-pair permuted
    for (int i4 = tid; i4 < KTR * (CC/4); i4 += 512) {
        int r = i4 / (CC/4), cq = i4 % (CC/4);
        int c0 = cq * 4;
        int base = r * AST + (c0 & ~7) + ((c0 >> 2) & 1);
        float4 v = make_float4(0.f, 0.f, 0.f, 0.f);
        if (r0 + r < NN) v = *(const float4*)&xb[(size_t)(r0 + r) * CC + c0];
        As[base + 0] = f2tf(v.x); As[base + 2] = f2tf(v.y);
        As[base + 4] = f2tf(v.z); As[base + 6] = f2tf(v.w);
    }

    float best0[KI], best1[KI]; int bidx0[KI], bidx1[KI];
    #pragma unroll
    for (int k = 0; k < KI; k++) {
        best0[k] = 3.4e38f; bidx0[k] = 0;
        best1[k] = 3.4e38f; bidx1[k] = 0;
    }

    int r1 = r0 + wrow + g, r2 = r1 + 8;
    int rc1 = (r1 < NN) ? r1 : (NN - 1);
    int rc2 = (r2 < NN) ? r2 : (NN - 1);

    for (int m0 = 0; m0 < NN; m0 += KTC) {
        for (int i4 = tid; i4 < KTC * (CC/4); i4 += 512) {
            int r = i4 / (CC/4), cq = i4 % (CC/4);
            int c0 = cq * 4;
            int base = r * AST + (c0 & ~7) + ((c0 >> 2) & 1);
            float4 v = make_float4(0.f, 0.f, 0.f, 0.f);
            if (m0 + r < NN) v = *(const float4*)&xb[(size_t)(m0 + r) * CC + c0];
            Bs[base + 0] = f2tf(v.x); Bs[base + 2] = f2tf(v.y);
            Bs[base + 4] = f2tf(v.z); Bs[base + 6] = f2tf(v.w);
        }
        __syncthreads();

        float C[8][4];
        #pragma unroll
        for (int f = 0; f < 8; f++)
            #pragma unroll
            for (int j = 0; j < 4; j++) C[f][j] = 0.f;

        for (int ks = 0; ks < 12; ks++) {
            int k0 = ks * 8;
            int offA = (wrow + g) * AST + k0 + 2*th;
            uint2 a01 = *(const uint2*)&As[offA];
            uint2 a23 = *(const uint2*)&As[offA + 8*AST];
            #pragma unroll
            for (int f = 0; f < 8; f++) {
                int offB = (cw*64 + f*8 + g) * AST + k0 + 2*th;
                uint2 bv = *(const uint2*)&Bs[offB];
                mma_tf32(C[f], a01.x, a23.x, a01.y, a23.y, bv.x, bv.y);
            }
        }

        // ---- selection straight from fragments
        #pragma unroll
        for (int f = 0; f < 8; f++) {
            int nb = cw * 64 + f * 8;
            if (m0 + nb < NN) {
                int gm = m0 + nb + 2 * th;
                float2 p1 = *(const float2*)&rp[(size_t)rc1 * NN + gm];
                float2 p2 = *(const float2*)&rp[(size_t)rc2 * NN + gm];
                ins12(best0, bidx0, p1.x - 2.f * C[f][0], gm);
                ins12(best0, bidx0, p1.y - 2.f * C[f][1], gm + 1);
                ins12(best1, bidx1, p2.x - 2.f * C[f][2], gm);
                ins12(best1, bidx1, p2.y - 2.f * C[f][3], gm + 1);
            }
        }
        __syncthreads();
    }

    // ---- write candidate lists (8 lists of KI per row, disjoint columns)
    int list = cw * 4 + th;
    if (r1 < NN) {
        int* op = cand + ((size_t)b * NN + r1) * NCAND + list * KI;
        #pragma unroll
        for (int k = 0; k < KI; k++) op[k] = bidx0[k];
    }
    if (r2 < NN) {
        int* op = cand + ((size_t)b * NN + r2) * NCAND + list * KI;
        #pragma unroll
        for (int k = 0; k < KI; k++) op[k] = bidx1[k];
    }
}

// ---------------- PASS 2: exact fp32 rescoring of 96 candidates + top-9
__global__ void __launch_bounds__(NCAND)
rescore_kernel(const float* __restrict__ xnt, const float* __restrict__ rp,
               const int* __restrict__ cand, int* __restrict__ idx)
{
    int n = blockIdx.x, b = blockIdx.y;
    int t = threadIdx.x;
    __shared__ float own[CC];
    __shared__ float sc[NCAND];
    __shared__ int   ci[NCAND];

    const float* xb = xnt + (size_t)b * NN * CC;
    own[t < CC ? t : 0] = xb[(size_t)n * CC + (t < CC ? t : 0)];
    __syncthreads();

    int c = cand[((size_t)b * NN + n) * NCAND + t];
    const float4* nb = (const float4*)&xb[(size_t)c * CC];
    float dot = 0.f;
    #pragma unroll
    for (int q = 0; q < CC/4; q++) {
        float4 v = __ldg(nb + q);
        dot += own[4*q]*v.x + own[4*q+1]*v.y + own[4*q+2]*v.z + own[4*q+3]*v.w;
    }
    sc[t] = __ldg(&rp[(size_t)n * NN + c]) - 2.f * dot;
    ci[t] = c;
    __syncthreads();

    if (t == 0) {
        int* op = idx + ((size_t)b * NN + n) * KK;
        #pragma unroll 1
        for (int k = 0; k < KK; k++) {
            float bv = 3.5e38f; int bi = 0x7fffffff; int bj = 0;
            for (int j = 0; j < NCAND; j++) {
                float v = sc[j];
                if (v < bv || (v == bv && ci[j] < bi)) { bv = v; bi = ci[j]; bj = j; }
            }
            op[k] = bi;
            sc[bj] = 3.5e38f;
        }
    }
}

// ---------------- max-relative gather (from transposed features) + interleaved concat
__global__ void gather2_kernel(const float* __restrict__ y1t, const int* __restrict__ idx,
                               float* __restrict__ cat)
{
    int b = blockIdx.y;
    int n = blockIdx.x * blockDim.x + threadIdx.x;
    if (n >= NN) return;
    const int* ib = idx + ((size_t)b * NN + n) * KK;
    int j[KK];
    #pragma unroll
    for (int k = 0; k < KK; k++) j[k] = ib[k];

    const float4* base = (const float4*)(y1t + (size_t)b * NN * CC);
    const float4* own  = base + (size_t)n * (CC/4);
    float* cb = cat + (size_t)b * 2 * CC * NN + n;

    #pragma unroll 2
    for (int cc = 0; cc < CC/4; cc++) {
        float4 o = own[cc];
        float4 m = base[(size_t)j[0] * (CC/4) + cc];
        #pragma unroll
        for (int k = 1; k < KK; k++) {
            float4 v = base[(size_t)j[k] * (CC/4) + cc];
            m.x = fmaxf(m.x, v.x); m.y = fmaxf(m.y, v.y);
            m.z = fmaxf(m.z, v.z); m.w = fmaxf(m.w, v.w);
        }
        cb[(size_t)(8*cc + 0) * NN] = o.x;
        cb[(size_t)(8*cc + 1) * NN] = m.x - o.x;
        cb[(size_t)(8*cc + 2) * NN] = o.y;
        cb[(size_t)(8*cc + 3) * NN] = m.y - o.y;
        cb[(size_t)(8*cc + 4) * NN] = o.z;
        cb[(size_t)(8*cc + 5) * NN] = m.z - o.z;
        cb[(size_t)(8*cc + 6) * NN] = o.w;
        cb[(size_t)(8*cc + 7) * NN] = m.w - o.w;
    }
}

// ---------------- host orchestration -----------------------------------------
static void run_grapher(const float* X, const float* rp,
                        const float* fc1w, const float* fc1b,
                        const float* mrw,  const float* mrb,
                        const float* fc2w, const float* fc2b,
                        float* out,
                        float* y1, float* y1t, float* xnt, int* cd, int* idx,
                        float* cat, float* y2, float* t)
{
    dim3 gA((NN + TN - 1) / TN, CC / TO, BB);
    gemm_bias_kernel<<<gA, 256>>>(X, fc1w, fc1b, y1, CC, CC);
    inorm_kernel<0><<<BB * CC, 256>>>(y1, y1, nullptr);
    colnorm_t_kernel<<<dim3((NN + 255) / 256, BB), 256>>>(y1, xnt);
    transpose_kernel<<<dim3((NN + 31) / 32, (CC + 31) / 32, BB), dim3(32, 8)>>>(y1, y1t);
    knn_mma_kernel<<<dim3((NN + KTR - 1) / KTR, BB), 512, SMEM_KNN>>>(xnt, rp, cd);
    rescore_kernel<<<dim3(NN, BB), NCAND>>>(xnt, rp, cd, idx);
    gather2_kernel<<<dim3((NN + 255) / 256, BB), 256>>>(y1t, idx, cat);
    dim3 gB((NN + TN - 1) / TN, 2 * CC / TO, BB);
    gemm_bias_kernel<<<gB, 256>>>(cat, mrw, mrb, y2, 2 * CC, 2 * CC);
    inorm_kernel<1><<<BB * 2 * CC, 256>>>(y2, y2, nullptr);
    dim3 gC((NN + TN - 1) / TN, CC / TO, BB);
    gemm_bias_kernel<<<gC, 256>>>(y2, fc2w, fc2b, t, 2 * CC, CC);
    inorm_kernel<3><<<BB * CC, 256>>>(t, out, X);
}

static void run_ffn(const float* X,
                    const float* w1, const float* b1,
                    const float* w2, const float* b2,
                    float* out, float* t, float* y1)
{
    dim3 gA((NN + TN - 1) / TN, 4 * CC / TO, BB);
    gemm_bias_kernel<<<gA, 256>>>(X, w1, b1, t, CC, 4 * CC);
    inorm_kernel<1><<<BB * 4 * CC, 256>>>(t, t, nullptr);
    dim3 gB((NN + TN - 1) / TN, CC / TO, BB);
    gemm_bias_kernel<<<gB, 256>>>(t, w2, b2, y1, 4 * CC, CC);
    inorm_kernel<3><<<BB * CC, 256>>>(y1, out, X);
}

extern "C" void kernel_launch(void* const* d_in, const int* in_sizes, int n_in,
                              void* d_out, int out_size)
{
    const float* X0 = (const float*)d_in[0];
    const float* rp = (const float*)d_in[1];

    float *y1, *y1t, *xnt, *cat, *y2, *t, *s1, *s2; int *cd, *idx;
    cudaGetSymbolAddress((void**)&y1,  g_y1);
    cudaGetSymbolAddress((void**)&y1t, g_y1t);
    cudaGetSymbolAddress((void**)&xnt, g_xnt);
    cudaGetSymbolAddress((void**)&cd,  g_cand);
    cudaGetSymbolAddress((void**)&idx, g_idx);
    cudaGetSymbolAddress((void**)&cat, g_cat);
    cudaGetSymbolAddress((void**)&y2,  g_y2);
    cudaGetSymbolAddress((void**)&t,   g_t);
    cudaGetSymbolAddress((void**)&s1,  g_s1);
    cudaGetSymbolAddress((void**)&s2,  g_s2);

    cudaFuncSetAttribute(knn_mma_kernel, cudaFuncAttributeMaxDynamicSharedMemorySize, SMEM_KNN);

    // grapher 1: X0 -> s1
    run_grapher(X0, rp,
                (const float*)d_in[2], (const float*)d_in[3],
                (const float*)d_in[4], (const float*)d_in[5],
                (const float*)d_in[6], (const float*)d_in[7],
                s1, y1, y1t, xnt, cd, idx, cat, y2, t);
    // ffn 1: s1 -> s2
    run_ffn(s1,
            (const float*)d_in[14], (const float*)d_in[15],
            (const float*)d_in[16], (const float*)d_in[17],
            s2, t, y1);
    // mid: relu(inorm(s2)) -> s1
    inorm_kernel<2><<<BB * CC, 256>>>(s2, s1, nullptr);
    // grapher 2: s1 -> s2
    run_grapher(s1, rp,
                (const float*)d_in[8],  (const float*)d_in[9],
                (const float*)d_in[10], (const float*)d_in[11],
                (const float*)d_in[12], (const float*)d_in[13],
                s2, y1, y1t, xnt, cd, idx, cat, y2, t);
    // ffn 2: s2 -> s1
    run_ffn(s2,
            (const float*)d_in[18], (const float*)d_in[19],
            (const float*)d_in[20], (const float*)d_in[21],
            s1, t, y1);
    // final: out = X0 + inorm(s1)
    inorm_kernel<3><<<BB * CC, 256>>>(s1, (float*)d_out, X0);
}

// round 7
// speedup vs baseline: 1.2200x; 1.2200x over previous
#include <cuda_runtime.h>
#include <cuda_pipeline.h>
#include <math.h>
#include <stdint.h>

#define BB 8
#define CC 96
#define NN 3136
#define KK 9
#define KI 12     // per-thread candidate list length (pass 1)
#define NCAND 96  // 8 lists * KI per row

// ---------------- scratch (device globals: no allocations allowed) ----------
__device__ float    g_y1[BB*CC*NN];
__device__ float    g_y1t[BB*NN*CC];
__device__ float    g_xnt[BB*NN*CC];     // fp32 normalized features (rescore)
__device__ unsigned g_xtf[BB*NN*CC];     // tf32 bits, column-permuted (pass 1)
__device__ int      g_cand[BB*NN*NCAND];
__device__ int      g_idx[BB*NN*KK];
__device__ float    g_cat[BB*2*CC*NN];
__device__ float    g_y2[BB*2*CC*NN];
__device__ float    g_t [BB*4*CC*NN];
__device__ float    g_s1[BB*CC*NN];
__device__ float    g_s2[BB*CC*NN];

// ---------------- generic 1x1-conv GEMM: out[b,o,n] = sum_c W[o,c] in[b,c,n] + bias[o]
#define TN 128
#define TO 32
#define TKC 32
__global__ void gemm_bias_kernel(const float* __restrict__ in, const float* __restrict__ W,
                                 const float* __restrict__ bias, float* __restrict__ out,
                                 int Cin, int Cout)
{
    int b  = blockIdx.z;
    int o0 = blockIdx.y * TO;
    int n0 = blockIdx.x * TN;
    const float* inb = in + (size_t)b * Cin * NN;
    float* outb      = out + (size_t)b * Cout * NN;

    __shared__ float Ws[TKC][TO + 1];
    __shared__ float Is[TKC][TN];

    int tid = threadIdx.x;
    int tx = tid & 31;
    int ty = tid >> 5;

    float acc[4][4];
    #pragma unroll
    for (int i = 0; i < 4; i++)
        #pragma unroll
        for (int j = 0; j < 4; j++) acc[i][j] = 0.f;

    for (int k0 = 0; k0 < Cin; k0 += TKC) {
        for (int i = tid; i < TO * TKC; i += 256) {
            int o = i >> 5, k = i & 31;
            Ws[k][o] = W[(size_t)(o0 + o) * Cin + k0 + k];
        }
        for (int i = tid; i < TKC * TN; i += 256) {
            int k = i >> 7, n = i & 127;
            int gn = n0 + n;
            Is[k][n] = (gn < NN) ? inb[(size_t)(k0 + k) * NN + gn] : 0.f;
        }
        __syncthreads();
        #pragma unroll 8
        for (int k = 0; k < TKC; k++) {
            float a0 = Ws[k][ty*4+0], a1 = Ws[k][ty*4+1];
            float a2 = Ws[k][ty*4+2], a3 = Ws[k][ty*4+3];
            float4 bv = *(const float4*)&Is[k][tx*4];
            acc[0][0] += a0*bv.x; acc[0][1] += a0*bv.y; acc[0][2] += a0*bv.z; acc[0][3] += a0*bv.w;
            acc[1][0] += a1*bv.x; acc[1][1] += a1*bv.y; acc[1][2] += a1*bv.z; acc[1][3] += a1*bv.w;
            acc[2][0] += a2*bv.x; acc[2][1] += a2*bv.y; acc[2][2] += a2*bv.z; acc[2][3] += a2*bv.w;
            acc[3][0] += a3*bv.x; acc[3][1] += a3*bv.y; acc[3][2] += a3*bv.z; acc[3][3] += a3*bv.w;
        }
        __syncthreads();
    }
    #pragma unroll
    for (int i = 0; i < 4; i++) {
        int o = o0 + ty*4 + i;
        float bb = bias[o];
        #pragma unroll
        for (int j = 0; j < 4; j++) {
            int n = n0 + tx*4 + j;
            if (n < NN) outb[(size_t)o * NN + n] = acc[i][j] + bb;
        }
    }
}

// ---------------- instance norm over N per (b,c) row, with fused epilogues
// EPI: 0=none, 1=gelu(exact), 2=relu, 3=add residual
#define NN4 (NN/4)
template<int EPI>
__global__ void inorm_kernel(const float* __restrict__ in, float* __restrict__ out,
                             const float* __restrict__ res)
{
    int row = blockIdx.x;
    const float4* x4 = (const float4*)(in + (size_t)row * NN);
    float4* y4       = (float4*)(out + (size_t)row * NN);
    const float4* r4 = res ? (const float4*)(res + (size_t)row * NN) : nullptr;

    float s = 0.f, ss = 0.f;
    for (int i = threadIdx.x; i < NN4; i += blockDim.x) {
        float4 v = x4[i];
        s  += v.x + v.y + v.z + v.w;
        ss += v.x*v.x + v.y*v.y + v.z*v.z + v.w*v.w;
    }
    __shared__ float red[2][32];
    #pragma unroll
    for (int o = 16; o; o >>= 1) {
        s  += __shfl_down_sync(0xffffffffu, s,  o);
        ss += __shfl_down_sync(0xffffffffu, ss, o);
    }
    int wid = threadIdx.x >> 5, lid = threadIdx.x & 31;
    if (!lid) { red[0][wid] = s; red[1][wid] = ss; }
    __syncthreads();
    if (wid == 0) {
        s  = (lid < (int)(blockDim.x >> 5)) ? red[0][lid] : 0.f;
        ss = (lid < (int)(blockDim.x >> 5)) ? red[1][lid] : 0.f;
        #pragma unroll
        for (int o = 16; o; o >>= 1) {
            s  += __shfl_down_sync(0xffffffffu, s,  o);
            ss += __shfl_down_sync(0xffffffffu, ss, o);
        }
        if (!lid) { red[0][0] = s; red[1][0] = ss; }
    }
    __syncthreads();
    float mean = red[0][0] * (1.f / NN);
    float var  = red[1][0] * (1.f / NN) - mean * mean;
    float rstd = rsqrtf(var + 1e-5f);
    for (int i = threadIdx.x; i < NN4; i += blockDim.x) {
        float4 v = x4[i];
        float o0 = (v.x - mean) * rstd, o1 = (v.y - mean) * rstd;
        float o2 = (v.z - mean) * rstd, o3 = (v.w - mean) * rstd;
        if (EPI == 1) {
            o0 = 0.5f*o0*(1.f + erff(o0*0.70710678118654752f));
            o1 = 0.5f*o1*(1.f + erff(o1*0.70710678118654752f));
            o2 = 0.5f*o2*(1.f + erff(o2*0.70710678118654752f));
            o3 = 0.5f*o3*(1.f + erff(o3*0.70710678118654752f));
        } else if (EPI == 2) {
            o0 = fmaxf(o0, 0.f); o1 = fmaxf(o1, 0.f);
            o2 = fmaxf(o2, 0.f); o3 = fmaxf(o3, 0.f);
        } else if (EPI == 3) {
            float4 r = r4[i];
            o0 += r.x; o1 += r.y; o2 += r.z; o3 += r.w;
        }
        y4[i] = make_float4(o0, o1, o2, o3);
    }
}

__device__ __forceinline__ unsigned f2tf(float v) {
    unsigned r;
    asm("cvt.rna.tf32.f32 %0, %1;" : "=r"(r) : "f"(v));
    return r;
}

// ---------------- per-pixel L2 norm -> fp32 [b][n][c] + permuted tf32 plane
__global__ void colnorm_t_kernel(const float* __restrict__ y1, float* __restrict__ xnt,
                                 unsigned* __restrict__ xtf)
{
    int b = blockIdx.y;
    int n = blockIdx.x * blockDim.x + threadIdx.x;
    if (n >= NN) return;
    const float* p = y1 + (size_t)b * CC * NN + n;
    float v[CC];
    float s = 0.f;
    #pragma unroll
    for (int c = 0; c < CC; c++) { v[c] = p[(size_t)c * NN]; s += v[c] * v[c]; }
    float rn = 1.f / fmaxf(sqrtf(s), 1e-12f);
    float4* q = (float4*)(xnt + ((size_t)b * NN + n) * CC);
    #pragma unroll
    for (int cq = 0; cq < CC/4; cq++)
        q[cq] = make_float4(v[4*cq]*rn, v[4*cq+1]*rn, v[4*cq+2]*rn, v[4*cq+3]*rn);
    // permuted tf32 plane: element c -> (c&~7) + 2*(c&3) + ((c>>2)&1)
    unsigned pw[CC];
    #pragma unroll
    for (int c = 0; c < CC; c++) {
        int pc = (c & ~7) + 2 * (c & 3) + ((c >> 2) & 1);
        pw[pc] = f2tf(v[c] * rn);
    }
    uint4* qt = (uint4*)(xtf + ((size_t)b * NN + n) * CC);
    #pragma unroll
    for (int g = 0; g < CC/4; g++)
        qt[g] = make_uint4(pw[4*g], pw[4*g+1], pw[4*g+2], pw[4*g+3]);
}

// ---------------- tiled transpose: [b][C][N] -> [b][N][C]
__global__ void transpose_kernel(const float* __restrict__ in, float* __restrict__ out)
{
    __shared__ float tile[32][33];
    int b  = blockIdx.z;
    int n0 = blockIdx.x * 32;
    int c0 = blockIdx.y * 32;
    int x = threadIdx.x, y = threadIdx.y;   // 32 x 8
    #pragma unroll
    for (int i = 0; i < 32; i += 8) {
        int c = c0 + y + i, n = n0 + x;
        tile[y + i][x] = (c < CC && n < NN) ? in[(size_t)b*CC*NN + (size_t)c*NN + n] : 0.f;
    }
    __syncthreads();
    #pragma unroll
    for (int i = 0; i < 32; i += 8) {
        int n = n0 + y + i, c = c0 + x;
        if (n < NN && c < CC)
            out[(size_t)b*NN*CC + (size_t)n*CC + c] = tile[x][y + i];
    }
}

// ---------------- PASS 1: tf32 MMA distance GEMM + per-thread top-12 candidates
// score(n,m) = rp[n,m] - 2*dot(xn_n, xn_m)  (sq terms == 1; ordering identical)
#define KTR 128
#define KTC 128
#define NT  ((NN + KTC - 1) / KTC)            // 25
#define AST 104                               // smem row stride (floats), conflict-free LDS.64
#define PL  (KTR*AST)
#define SMEM_KNN (3 * PL * 4)                 // A + 2x B (double buffer)

__device__ __forceinline__ void mma_tf32(float c[4],
    unsigned a0, unsigned a1, unsigned a2, unsigned a3, unsigned b0, unsigned b1)
{
    asm volatile(
        "mma.sync.aligned.m16n8k8.row.col.f32.tf32.tf32.f32 "
        "{%0,%1,%2,%3},{%4,%5,%6,%7},{%8,%9},{%0,%1,%2,%3};"
        : "+f"(c[0]), "+f"(c[1]), "+f"(c[2]), "+f"(c[3])
        : "r"(a0), "r"(a1), "r"(a2), "r"(a3), "r"(b0), "r"(b1));
}

__device__ __forceinline__ void ins12(float (&bv)[KI], int (&bi)[KI], float s, int c)
{
    if (s < bv[KI-1]) {
        bv[KI-1] = s; bi[KI-1] = c;
        #pragma unroll
        for (int k = KI-1; k > 0; k--) {
            if (bv[k] < bv[k-1]) {
                float tv = bv[k]; bv[k] = bv[k-1]; bv[k-1] = tv;
                int   ti = bi[k]; bi[k] = bi[k-1]; bi[k-1] = ti;
            }
        }
    }
}

__global__ void __launch_bounds__(512, 1)
knn_mma_kernel(const unsigned* __restrict__ xtf, const float* __restrict__ rp,
               int* __restrict__ cand)
{
    extern __shared__ unsigned smu[];
    unsigned* As = smu;
    unsigned* Bs[2] = { smu + PL, smu + 2 * PL };

    int b  = blockIdx.y;
    int r0 = blockIdx.x * KTR;
    const uint4* xb4 = (const uint4*)(xtf + (size_t)b * NN * CC);   // 24 uint4 per row
    int tid  = threadIdx.x;
    int warp = tid >> 5, lane = tid & 31;
    int g = lane >> 2, th = lane & 3;
    int wrow = (warp >> 1) * 16;
    int cw   = warp & 1;

    // ---- stage A tile (plain copy, once)
    for (int i = tid; i < KTR * 24; i += 512) {
        int r = i / 24, gq = i % 24;
        int gr = r0 + r; if (gr >= NN) gr = NN - 1;
        *(uint4*)&As[r * AST + gq * 4] = __ldg(xb4 + (size_t)gr * 24 + gq);
    }

    // ---- prefetch B tile 0 via cp.async
    {
        unsigned* Bd = Bs[0];
        for (int i = tid; i < KTC * 24; i += 512) {
            int r = i / 24, gq = i % 24;
            int src = r; if (src >= NN) src = NN - 1;
            __pipeline_memcpy_async(&Bd[r * AST + gq * 4], xb4 + (size_t)src * 24 + gq, 16);
        }
        __pipeline_commit();
    }

    float best0[KI], best1[KI]; int bidx0[KI], bidx1[KI];
    #pragma unroll
    for (int k = 0; k < KI; k++) {
        best0[k] = 3.4e38f; bidx0[k] = 0;
        best1[k] = 3.4e38f; bidx1[k] = 0;
    }

    int r1 = r0 + wrow + g, r2 = r1 + 8;
    int rc1 = (r1 < NN) ? r1 : (NN - 1);
    int rc2 = (r2 < NN) ? r2 : (NN - 1);

    for (int t = 0; t < NT; t++) {
        int m0 = t * KTC;
        if (t + 1 < NT) {
            unsigned* Bd = Bs[(t + 1) & 1];
            int m1 = (t + 1) * KTC;
            for (int i = tid; i < KTC * 24; i += 512) {
                int r = i / 24, gq = i % 24;
                int src = m1 + r; if (src >= NN) src = NN - 1;
                __pipeline_memcpy_async(&Bd[r * AST + gq * 4], xb4 + (size_t)src * 24 + gq, 16);
            }
            __pipeline_commit();
            __pipeline_wait_prior(1);
        } else {
            __pipeline_wait_prior(0);
        }
        __syncthreads();

        const unsigned* Bc = Bs[t & 1];
        float C[8][4];
        #pragma unroll
        for (int f = 0; f < 8; f++)
            #pragma unroll
            for (int j = 0; j < 4; j++) C[f][j] = 0.f;

        for (int ks = 0; ks < 12; ks++) {
            int k0 = ks * 8;
            int offA = (wrow + g) * AST + k0 + 2*th;
            uint2 a01 = *(const uint2*)&As[offA];
            uint2 a23 = *(const uint2*)&As[offA + 8*AST];
            #pragma unroll
            for (int f = 0; f < 8; f++) {
                int offB = (cw*64 + f*8 + g) * AST + k0 + 2*th;
                uint2 bv = *(const uint2*)&Bc[offB];
                mma_tf32(C[f], a01.x, a23.x, a01.y, a23.y, bv.x, bv.y);
            }
        }

        // ---- selection straight from fragments
        #pragma unroll
        for (int f = 0; f < 8; f++) {
            int nb = cw * 64 + f * 8;
            if (m0 + nb < NN) {
                int gm = m0 + nb + 2 * th;
                float2 p1 = *(const float2*)&rp[(size_t)rc1 * NN + gm];
                float2 p2 = *(const float2*)&rp[(size_t)rc2 * NN + gm];
                ins12(best0, bidx0, p1.x - 2.f * C[f][0], gm);
                ins12(best0, bidx0, p1.y - 2.f * C[f][1], gm + 1);
                ins12(best1, bidx1, p2.x - 2.f * C[f][2], gm);
                ins12(best1, bidx1, p2.y - 2.f * C[f][3], gm + 1);
            }
        }
        __syncthreads();
    }

    // ---- write candidate lists (8 lists of KI per row, disjoint columns)
    int list = cw * 4 + th;
    if (r1 < NN) {
        int* op = cand + ((size_t)b * NN + r1) * NCAND + list * KI;
        #pragma unroll
        for (int k = 0; k < KI; k++) op[k] = bidx0[k];
    }
    if (r2 < NN) {
        int* op = cand + ((size_t)b * NN + r2) * NCAND + list * KI;
        #pragma unroll
        for (int k = 0; k < KI; k++) op[k] = bidx1[k];
    }
}

// ---------------- PASS 2: exact fp32 rescoring, warp-per-row
__global__ void __launch_bounds__(256)
rescore_kernel(const float* __restrict__ xnt, const float* __restrict__ rp,
               const int* __restrict__ cand, int* __restrict__ idx)
{
    int warp = threadIdx.x >> 5, lane = threadIdx.x & 31;
    int n = blockIdx.x * 8 + warp;
    int b = blockIdx.y;
    const float* xb = xnt + (size_t)b * NN * CC;

    __shared__ float own[8][CC];
    for (int c = lane; c < CC; c += 32) own[warp][c] = xb[(size_t)n * CC + c];
    __syncwarp();

    float sc[3]; int ci[3];
    const int* cp = cand + ((size_t)b * NN + n) * NCAND;
    #pragma unroll
    for (int s = 0; s < 3; s++) {
        int c = cp[s * 32 + lane];
        const float4* nb = (const float4*)&xb[(size_t)c * CC];
        float dot = 0.f;
        #pragma unroll
        for (int q = 0; q < CC/4; q++) {
            float4 v = __ldg(nb + q);
            dot += own[warp][4*q]*v.x + own[warp][4*q+1]*v.y
                 + own[warp][4*q+2]*v.z + own[warp][4*q+3]*v.w;
        }
        sc[s] = __ldg(&rp[(size_t)n * NN + c]) - 2.f * dot;
        ci[s] = c;
    }

    int* op = idx + ((size_t)b * NN + n) * KK;
    #pragma unroll 1
    for (int k = 0; k < KK; k++) {
        // local min of 3
        float bv = sc[0]; int bi = ci[0];
        if (sc[1] < bv || (sc[1] == bv && ci[1] < bi)) { bv = sc[1]; bi = ci[1]; }
        if (sc[2] < bv || (sc[2] == bv && ci[2] < bi)) { bv = sc[2]; bi = ci[2]; }
        // warp argmin
        #pragma unroll
        for (int o = 16; o; o >>= 1) {
            float ov = __shfl_down_sync(0xffffffffu, bv, o);
            int   oi = __shfl_down_sync(0xffffffffu, bi, o);
            if (ov < bv || (ov == bv && oi < bi)) { bv = ov; bi = oi; }
        }
        bi = __shfl_sync(0xffffffffu, bi, 0);
        if (lane == 0) op[k] = bi;
        // invalidate winner (indices unique across disjoint subsets)
        #pragma unroll
        for (int s = 0; s < 3; s++) if (ci[s] == bi) sc[s] = 3.5e38f;
    }
}

// ---------------- max-relative gather (from transposed features) + interleaved concat
__global__ void gather2_kernel(const float* __restrict__ y1t, const int* __restrict__ idx,
                               float* __restrict__ cat)
{
    int b = blockIdx.y;
    int n = blockIdx.x * blockDim.x + threadIdx.x;
    if (n >= NN) return;
    const int* ib = idx + ((size_t)b * NN + n) * KK;
    int j[KK];
    #pragma unroll
    for (int k = 0; k < KK; k++) j[k] = ib[k];

    const float4* base = (const float4*)(y1t + (size_t)b * NN * CC);
    const float4* own  = base + (size_t)n * (CC/4);
    float* cb = cat + (size_t)b * 2 * CC * NN + n;

    #pragma unroll 2
    for (int cc = 0; cc < CC/4; cc++) {
        float4 o = own[cc];
        float4 m = base[(size_t)j[0] * (CC/4) + cc];
        #pragma unroll
        for (int k = 1; k < KK; k++) {
            float4 v = base[(size_t)j[k] * (CC/4) + cc];
            m.x = fmaxf(m.x, v.x); m.y = fmaxf(m.y, v.y);
            m.z = fmaxf(m.z, v.z); m.w = fmaxf(m.w, v.w);
        }
        cb[(size_t)(8*cc + 0) * NN] = o.x;
        cb[(size_t)(8*cc + 1) * NN] = m.x - o.x;
        cb[(size_t)(8*cc + 2) * NN] = o.y;
        cb[(size_t)(8*cc + 3) * NN] = m.y - o.y;
        cb[(size_t)(8*cc + 4) * NN] = o.z;
        cb[(size_t)(8*cc + 5) * NN] = m.z - o.z;
        cb[(size_t)(8*cc + 6) * NN] = o.w;
        cb[(size_t)(8*cc + 7) * NN] = m.w - o.w;
    }
}

// ---------------- host orchestration -----------------------------------------
static void run_grapher(const float* X, const float* rp,
                        const float* fc1w, const float* fc1b,
                        const float* mrw,  const float* mrb,
                        const float* fc2w, const float* fc2b,
                        float* out,
                        float* y1, float* y1t, float* xnt, unsigned* xtf,
                        int* cd, int* idx, float* cat, float* y2, float* t)
{
    dim3 gA((NN + TN - 1) / TN, CC / TO, BB);
    gemm_bias_kernel<<<gA, 256>>>(X, fc1w, fc1b, y1, CC, CC);
    inorm_kernel<0><<<BB * CC, 256>>>(y1, y1, nullptr);
    colnorm_t_kernel<<<dim3((NN + 255) / 256, BB), 256>>>(y1, xnt, xtf);
    transpose_kernel<<<dim3((NN + 31) / 32, (CC + 31) / 32, BB), dim3(32, 8)>>>(y1, y1t);
    knn_mma_kernel<<<dim3((NN + KTR - 1) / KTR, BB), 512, SMEM_KNN>>>(xtf, rp, cd);
    rescore_kernel<<<dim3(NN / 8, BB), 256>>>(xnt, rp, cd, idx);
    gather2_kernel<<<dim3((NN + 255) / 256, BB), 256>>>(y1t, idx, cat);
    dim3 gB((NN + TN - 1) / TN, 2 * CC / TO, BB);
    gemm_bias_kernel<<<gB, 256>>>(cat, mrw, mrb, y2, 2 * CC, 2 * CC);
    inorm_kernel<1><<<BB * 2 * CC, 256>>>(y2, y2, nullptr);
    dim3 gC((NN + TN - 1) / TN, CC / TO, BB);
    gemm_bias_kernel<<<gC, 256>>>(y2, fc2w, fc2b, t, 2 * CC, CC);
    inorm_kernel<3><<<BB * CC, 256>>>(t, out, X);
}

static void run_ffn(const float* X,
                    const float* w1, const float* b1,
                    const float* w2, const float* b2,
                    float* out, float* t, float* y1)
{
    dim3 gA((NN + TN - 1) / TN, 4 * CC / TO, BB);
    gemm_bias_kernel<<<gA, 256>>>(X, w1, b1, t, CC, 4 * CC);
    inorm_kernel<1><<<BB * 4 * CC, 256>>>(t, t, nullptr);
    dim3 gB((NN + TN - 1) / TN, CC / TO, BB);
    gemm_bias_kernel<<<gB, 256>>>(t, w2, b2, y1, 4 * CC, CC);
    inorm_kernel<3><<<BB * CC, 256>>>(y1, out, X);
}

extern "C" void kernel_launch(void* const* d_in, const int* in_sizes, int n_in,
                              void* d_out, int out_size)
{
    const float* X0 = (const float*)d_in[0];
    const float* rp = (const float*)d_in[1];

    float *y1, *y1t, *xnt, *cat, *y2, *t, *s1, *s2; int *cd, *idx; unsigned* xtf;
    cudaGetSymbolAddress((void**)&y1,  g_y1);
    cudaGetSymbolAddress((void**)&y1t, g_y1t);
    cudaGetSymbolAddress((void**)&xnt, g_xnt);
    cudaGetSymbolAddress((void**)&xtf, g_xtf);
    cudaGetSymbolAddress((void**)&cd,  g_cand);
    cudaGetSymbolAddress((void**)&idx, g_idx);
    cudaGetSymbolAddress((void**)&cat, g_cat);
    cudaGetSymbolAddress((void**)&y2,  g_y2);
    cudaGetSymbolAddress((void**)&t,   g_t);
    cudaGetSymbolAddress((void**)&s1,  g_s1);
    cudaGetSymbolAddress((void**)&s2,  g_s2);

    cudaFuncSetAttribute(knn_mma_kernel, cudaFuncAttributeMaxDynamicSharedMemorySize, SMEM_KNN);

    // grapher 1: X0 -> s1
    run_grapher(X0, rp,
                (const float*)d_in[2], (const float*)d_in[3],
                (const float*)d_in[4], (const float*)d_in[5],
                (const float*)d_in[6], (const float*)d_in[7],
                s1, y1, y1t, xnt, xtf, cd, idx, cat, y2, t);
    // ffn 1: s1 -> s2
    run_ffn(s1,
            (const float*)d_in[14], (const float*)d_in[15],
            (const float*)d_in[16], (const float*)d_in[17],
            s2, t, y1);
    // mid: relu(inorm(s2)) -> s1
    inorm_kernel<2><<<BB * CC, 256>>>(s2, s1, nullptr);
    // grapher 2: s1 -> s2
    run_grapher(s1, rp,
                (const float*)d_in[8],  (const float*)d_in[9],
                (const float*)d_in[10], (const float*)d_in[11],
                (const float*)d_in[12], (const float*)d_in[13],
                s2, y1, y1t, xnt, xtf, cd, idx, cat, y2, t);
    // ffn 2: s2 -> s1
    run_ffn(s2,
            (const float*)d_in[18], (const float*)d_in[19],
            (const float*)d_in[20], (const float*)d_in[21],
            s1, t, y1);
    // final: out = X0 + inorm(s1)
    inorm_kernel<3><<<BB * CC, 256>>>(s1, (float*)d_out, X0);
}